// round 3
// baseline (speedup 1.0000x reference)
#include <cuda_runtime.h>
#include <cstdint>

// Problem constants (N = 262144, D = 64, K = 512)
#define NROWS 262144
#define DIM   64
#define KCB   512

#define THREADS 512
#define ROWS_PER_BLOCK THREADS          // 1 row per thread
#define BLOCKS (NROWS / ROWS_PER_BLOCK) // 512

// smem: W (K*D floats) + w2 (K floats)
#define SMEM_FLOATS (KCB * DIM + KCB)
#define SMEM_BYTES  (SMEM_FLOATS * sizeof(float))

__device__ double   g_partials[BLOCKS];
__device__ unsigned g_ticket;   // zero-initialized; last block resets to 0

// ---- packed f32x2 helpers (ptxas will not auto-fuse; must be inline PTX) ----
__device__ __forceinline__ unsigned long long fma2(unsigned long long a,
                                                   unsigned long long b,
                                                   unsigned long long c) {
    unsigned long long d;
    asm("fma.rn.f32x2 %0, %1, %2, %3;" : "=l"(d) : "l"(a), "l"(b), "l"(c));
    return d;
}
__device__ __forceinline__ unsigned long long add2(unsigned long long a,
                                                   unsigned long long b) {
    unsigned long long d;
    asm("add.rn.f32x2 %0, %1, %2;" : "=l"(d) : "l"(a), "l"(b));
    return d;
}
__device__ __forceinline__ float lo32(unsigned long long v) {
    return __uint_as_float((unsigned)(v & 0xFFFFFFFFull));
}
__device__ __forceinline__ float hi32(unsigned long long v) {
    return __uint_as_float((unsigned)(v >> 32));
}

__global__ __launch_bounds__(THREADS, 1)
void vq_kernel(const float* __restrict__ enc,
               const float* __restrict__ W,
               float* __restrict__ out) {
    extern __shared__ float smem[];
    float* sW  = smem;              // K*D
    float* sw2 = smem + KCB * DIM;  // K

    const int tid = threadIdx.x;

    // Cooperative load of full codebook into smem (128 KB)
    {
        const float4* Wg  = (const float4*)W;
        float4*       sW4 = (float4*)sW;
        #pragma unroll
        for (int i = tid; i < (KCB * DIM) / 4; i += THREADS) sW4[i] = Wg[i];
    }
    __syncthreads();

    // w2[k] = sum_i fl(w*w), sequential (mirrors jnp.sum(weight*weight, axis=1))
    for (int k = tid; k < KCB; k += THREADS) {
        const float* wr = sW + k * DIM;
        float s = 0.0f;
        #pragma unroll
        for (int i = 0; i < DIM; i++) s = __fadd_rn(s, __fmul_rn(wr[i], wr[i]));
        sw2[k] = s;
    }
    __syncthreads();

    const int row = blockIdx.x * ROWS_PER_BLOCK + tid;

    // Load x row (64 floats) as 32 packed f32x2 registers
    unsigned long long xp[32];
    {
        const ulonglong2* xr = (const ulonglong2*)(enc + (size_t)row * DIM);
        #pragma unroll
        for (int j = 0; j < 16; j++) {
            ulonglong2 v = xr[j];
            xp[2 * j]     = v.x;
            xp[2 * j + 1] = v.y;
        }
    }

    // x2: sequential fp32 mul-then-add (match reference elementwise semantics)
    float x2 = 0.0f;
    #pragma unroll
    for (int j = 0; j < 32; j++) {
        float a = lo32(xp[j]);
        float b = hi32(xp[j]);
        x2 = __fadd_rn(x2, __fmul_rn(a, a));
        x2 = __fadd_rn(x2, __fmul_rn(b, b));
    }

    float best = __int_as_float(0x7f800000);  // +inf
    int   bi   = 0;

    #pragma unroll 2
    for (int k = 0; k < KCB; k++) {
        const ulonglong2* wr = (const ulonglong2*)(sW + k * DIM);
        unsigned long long a0 = 0ull, a1 = 0ull, a2 = 0ull, a3 = 0ull;
        #pragma unroll
        for (int j = 0; j < 16; j += 4) {
            ulonglong2 w0 = wr[j];
            ulonglong2 w1 = wr[j + 1];
            ulonglong2 w2 = wr[j + 2];
            ulonglong2 w3 = wr[j + 3];
            a0 = fma2(xp[2 * j],     w0.x, a0);
            a1 = fma2(xp[2 * j + 1], w0.y, a1);
            a2 = fma2(xp[2 * j + 2], w1.x, a2);
            a3 = fma2(xp[2 * j + 3], w1.y, a3);
            a0 = fma2(xp[2 * j + 4], w2.x, a0);
            a1 = fma2(xp[2 * j + 5], w2.y, a1);
            a2 = fma2(xp[2 * j + 6], w3.x, a2);
            a3 = fma2(xp[2 * j + 7], w3.y, a3);
        }
        float w2k = sw2[k];
        unsigned long long s = add2(add2(a0, a1), add2(a2, a3));
        float dot = __fadd_rn(lo32(s), hi32(s));
        // d = fl(fl(x2 - fl(2*dot)) + w2[k])  — exact reference op order
        float d = __fadd_rn(__fsub_rn(x2, __fmul_rn(2.0f, dot)), w2k);
        if (d < best) { best = d; bi = k; }   // strict < keeps first occurrence
    }

    // --- outputs ---
    out[row] = (float)bi;  // idx as float32

    // Gather q from GLOBAL W (L1/L2-hot), avoids same-column smem conflicts
    const float4* qg = (const float4*)(W + (size_t)bi * DIM);
    float* o = out + NROWS + (size_t)row * DIM;
    double lsum = 0.0;
    #pragma unroll
    for (int j = 0; j < 16; j++) {
        float4 q = __ldg(&qg[j]);
        float x0 = lo32(xp[2 * j]);
        float x1 = hi32(xp[2 * j]);
        float x2c = lo32(xp[2 * j + 1]);
        float x3 = hi32(xp[2 * j + 1]);
        float d0 = __fsub_rn(q.x, x0);
        float d1 = __fsub_rn(q.y, x1);
        float d2 = __fsub_rn(q.z, x2c);
        float d3 = __fsub_rn(q.w, x3);
        float4 rr;
        rr.x = __fadd_rn(x0,  d0);   // straight-through: fl(x + fl(q - x))
        rr.y = __fadd_rn(x1,  d1);
        rr.z = __fadd_rn(x2c, d2);
        rr.w = __fadd_rn(x3,  d3);
        ((float4*)o)[j] = rr;
        lsum += (double)__fmul_rn(d0, d0);
        lsum += (double)__fmul_rn(d1, d1);
        lsum += (double)__fmul_rn(d2, d2);
        lsum += (double)__fmul_rn(d3, d3);
    }

    // block reduction of lsum (warp shuffles, then smem across 16 warps)
    #pragma unroll
    for (int off = 16; off > 0; off >>= 1)
        lsum += __shfl_xor_sync(0xFFFFFFFFu, lsum, off);

    __syncthreads();   // done reading sW; reuse smem for reduction
    double* swarp = (double*)smem;
    if ((tid & 31) == 0) swarp[tid >> 5] = lsum;
    __syncthreads();

    __shared__ bool s_last;
    if (tid == 0) {
        double bsum = 0.0;
        #pragma unroll
        for (int w = 0; w < THREADS / 32; w++) bsum += swarp[w];
        g_partials[blockIdx.x] = bsum;
        __threadfence();
        unsigned old = atomicAdd(&g_ticket, 1u);
        s_last = (old == BLOCKS - 1);
    }
    __syncthreads();

    // Last block finalizes the loss (and resets the ticket for the next replay)
    if (s_last) {
        double t = 0.0;
        for (int i = tid; i < BLOCKS; i += THREADS) t += g_partials[i];
        #pragma unroll
        for (int off = 16; off > 0; off >>= 1)
            t += __shfl_xor_sync(0xFFFFFFFFu, t, off);
        if ((tid & 31) == 0) swarp[tid >> 5] = t;
        __syncthreads();
        if (tid == 0) {
            double tot = 0.0;
            #pragma unroll
            for (int w = 0; w < THREADS / 32; w++) tot += swarp[w];
            float m = (float)(tot / (double)((size_t)NROWS * DIM));
            // vq_loss = fl(fl(mean*0.25) + mean)
            out[(size_t)NROWS * (DIM + 1)] = __fadd_rn(__fmul_rn(m, 0.25f), m);
            g_ticket = 0;            // deterministic across graph replays
        }
    }
}

extern "C" void kernel_launch(void* const* d_in, const int* in_sizes, int n_in,
                              void* d_out, int out_size) {
    const float* enc = (const float*)d_in[0];   // [N, 64] fp32
    const float* W   = (const float*)d_in[1];   // [512, 64] fp32
    float* out = (float*)d_out;                 // [N | N*64 | 1] fp32

    cudaFuncSetAttribute(vq_kernel,
                         cudaFuncAttributeMaxDynamicSharedMemorySize, SMEM_BYTES);
    vq_kernel<<<BLOCKS, THREADS, SMEM_BYTES>>>(enc, W, out);
}

// round 4
// speedup vs baseline: 1.2626x; 1.2626x over previous
#include <cuda_runtime.h>
#include <cstdint>

// Problem constants (N = 262144, D = 64, K = 512)
#define NROWS 262144
#define DIM   64
#define KCB   512

// ---- Pass 1: K split in half across CTAs ----
#define KHALF   (KCB / 2)            // 256 codewords per CTA
#define T1      128                  // threads, pass 1
#define RPT     2                    // rows per thread
#define ROWS_PB (T1 * RPT)           // 256 rows per block
#define RBLK    (NROWS / ROWS_PB)    // 1024 row-blocks (x-dim), 2 halves (y-dim)

// smem pass 1: W half (KHALF*DIM) + w2 half (KHALF)
#define SMEM1_FLOATS (KHALF * DIM + KHALF)
#define SMEM1_BYTES  (SMEM1_FLOATS * sizeof(float))

// ---- Pass 2 ----
#define T2      256
#define BLOCKS2 (NROWS / T2)         // 1024

// Scratch (static device memory — allocation-free)
__device__ float    g_dbest[2][NROWS];
__device__ int      g_ibest[2][NROWS];
__device__ double   g_partials[BLOCKS2];
__device__ unsigned g_ticket;        // zero-init; last pass-2 block resets to 0

// ---- packed f32x2 helpers (ptxas will not auto-fuse; must be inline PTX) ----
__device__ __forceinline__ unsigned long long fma2(unsigned long long a,
                                                   unsigned long long b,
                                                   unsigned long long c) {
    unsigned long long d;
    asm("fma.rn.f32x2 %0, %1, %2, %3;" : "=l"(d) : "l"(a), "l"(b), "l"(c));
    return d;
}
__device__ __forceinline__ unsigned long long add2(unsigned long long a,
                                                   unsigned long long b) {
    unsigned long long d;
    asm("add.rn.f32x2 %0, %1, %2;" : "=l"(d) : "l"(a), "l"(b));
    return d;
}
__device__ __forceinline__ float lo32(unsigned long long v) {
    return __uint_as_float((unsigned)(v & 0xFFFFFFFFull));
}
__device__ __forceinline__ float hi32(unsigned long long v) {
    return __uint_as_float((unsigned)(v >> 32));
}

// ============================ Pass 1 ============================
__global__ __launch_bounds__(T1, 3)
void vq_pass1(const float* __restrict__ enc,
              const float* __restrict__ W) {
    extern __shared__ float smem[];
    float* sW  = smem;                 // KHALF * DIM
    float* sw2 = smem + KHALF * DIM;   // KHALF

    const int tid  = threadIdx.x;
    const int half = blockIdx.y;       // 0 or 1
    const int kofs = half * KHALF;

    // Cooperative load of this half of the codebook into smem (64 KB)
    {
        const float4* Wg  = (const float4*)(W + (size_t)kofs * DIM);
        float4*       sW4 = (float4*)sW;
        #pragma unroll
        for (int i = tid; i < (KHALF * DIM) / 4; i += T1) sW4[i] = Wg[i];
    }
    __syncthreads();

    // w2[k]: sequential fp32 mul-then-add (matches jnp.sum(w*w, axis=1))
    for (int k = tid; k < KHALF; k += T1) {
        const float* wr = sW + k * DIM;
        float s = 0.0f;
        #pragma unroll
        for (int i = 0; i < DIM; i++) s = __fadd_rn(s, __fmul_rn(wr[i], wr[i]));
        sw2[k] = s;
    }
    __syncthreads();

    const int row0 = blockIdx.x * ROWS_PB + tid;
    const int row1 = row0 + T1;

    // Load both x rows as packed f32x2 registers
    unsigned long long xa[32], xb[32];
    {
        const ulonglong2* r0 = (const ulonglong2*)(enc + (size_t)row0 * DIM);
        #pragma unroll
        for (int j = 0; j < 16; j++) {
            ulonglong2 v = r0[j];
            xa[2 * j] = v.x; xa[2 * j + 1] = v.y;
        }
        const ulonglong2* r1 = (const ulonglong2*)(enc + (size_t)row1 * DIM);
        #pragma unroll
        for (int j = 0; j < 16; j++) {
            ulonglong2 v = r1[j];
            xb[2 * j] = v.x; xb[2 * j + 1] = v.y;
        }
    }

    // x2: sequential fp32 mul-then-add (matches reference op order)
    float x2a = 0.0f, x2b = 0.0f;
    #pragma unroll
    for (int j = 0; j < 32; j++) {
        float a0 = lo32(xa[j]), a1 = hi32(xa[j]);
        x2a = __fadd_rn(x2a, __fmul_rn(a0, a0));
        x2a = __fadd_rn(x2a, __fmul_rn(a1, a1));
    }
    #pragma unroll
    for (int j = 0; j < 32; j++) {
        float b0 = lo32(xb[j]), b1 = hi32(xb[j]);
        x2b = __fadd_rn(x2b, __fmul_rn(b0, b0));
        x2b = __fadd_rn(x2b, __fmul_rn(b1, b1));
    }

    float bestA = __int_as_float(0x7f800000);
    float bestB = __int_as_float(0x7f800000);
    int   biA = 0, biB = 0;

    #pragma unroll 2
    for (int k = 0; k < KHALF; k++) {
        const ulonglong2* wr = (const ulonglong2*)(sW + k * DIM);
        unsigned long long a0 = 0ull, a1 = 0ull, a2 = 0ull, a3 = 0ull;
        unsigned long long b0 = 0ull, b1 = 0ull, b2 = 0ull, b3 = 0ull;
        #pragma unroll
        for (int j = 0; j < 16; j += 2) {
            ulonglong2 w0 = wr[j];
            ulonglong2 w1 = wr[j + 1];
            a0 = fma2(xa[2 * j],     w0.x, a0);
            b0 = fma2(xb[2 * j],     w0.x, b0);
            a1 = fma2(xa[2 * j + 1], w0.y, a1);
            b1 = fma2(xb[2 * j + 1], w0.y, b1);
            a2 = fma2(xa[2 * j + 2], w1.x, a2);
            b2 = fma2(xb[2 * j + 2], w1.x, b2);
            a3 = fma2(xa[2 * j + 3], w1.y, a3);
            b3 = fma2(xb[2 * j + 3], w1.y, b3);
        }
        float w2k = sw2[k];
        unsigned long long sa = add2(add2(a0, a1), add2(a2, a3));
        unsigned long long sb = add2(add2(b0, b1), add2(b2, b3));
        float dotA = __fadd_rn(lo32(sa), hi32(sa));
        float dotB = __fadd_rn(lo32(sb), hi32(sb));
        // d = fl(fl(x2 - fl(2*dot)) + w2[k])  — exact reference op order
        float dA = __fadd_rn(__fsub_rn(x2a, __fmul_rn(2.0f, dotA)), w2k);
        float dB = __fadd_rn(__fsub_rn(x2b, __fmul_rn(2.0f, dotB)), w2k);
        if (dA < bestA) { bestA = dA; biA = k; }   // strict < = first occurrence
        if (dB < bestB) { bestB = dB; biB = k; }
    }

    g_dbest[half][row0] = bestA;
    g_ibest[half][row0] = kofs + biA;
    g_dbest[half][row1] = bestB;
    g_ibest[half][row1] = kofs + biB;
}

// ============================ Pass 2 ============================
__global__ __launch_bounds__(T2, 4)
void vq_pass2(const float* __restrict__ enc,
              const float* __restrict__ W,
              float* __restrict__ out) {
    const int tid = threadIdx.x;
    const int row = blockIdx.x * T2 + tid;

    float dA = g_dbest[0][row];
    float dB = g_dbest[1][row];
    int   iA = g_ibest[0][row];
    int   iB = g_ibest[1][row];
    // Global first-occurrence tie-break: half 0 (lower k) wins ties.
    int bi = (dA <= dB) ? iA : iB;

    out[row] = (float)bi;

    const float4* xg = (const float4*)(enc + (size_t)row * DIM);
    const float4* qg = (const float4*)(W + (size_t)bi * DIM);
    float* o = out + NROWS + (size_t)row * DIM;

    double lsum = 0.0;
    #pragma unroll
    for (int j = 0; j < 16; j++) {
        float4 x = xg[j];
        float4 q = __ldg(&qg[j]);
        float d0 = __fsub_rn(q.x, x.x);
        float d1 = __fsub_rn(q.y, x.y);
        float d2 = __fsub_rn(q.z, x.z);
        float d3 = __fsub_rn(q.w, x.w);
        float4 rr;
        rr.x = __fadd_rn(x.x, d0);     // straight-through: fl(x + fl(q - x))
        rr.y = __fadd_rn(x.y, d1);
        rr.z = __fadd_rn(x.z, d2);
        rr.w = __fadd_rn(x.w, d3);
        o[0] = rr.x;  // keep vector store:
        ((float4*)o)[0] = rr;
        o += 4;
        lsum += (double)__fmul_rn(d0, d0);
        lsum += (double)__fmul_rn(d1, d1);
        lsum += (double)__fmul_rn(d2, d2);
        lsum += (double)__fmul_rn(d3, d3);
    }

    // block reduction (shuffle + smem across 8 warps)
    #pragma unroll
    for (int off = 16; off > 0; off >>= 1)
        lsum += __shfl_xor_sync(0xFFFFFFFFu, lsum, off);

    __shared__ double swarp[T2 / 32];
    __shared__ bool s_last;
    if ((tid & 31) == 0) swarp[tid >> 5] = lsum;
    __syncthreads();

    if (tid == 0) {
        double bsum = 0.0;
        #pragma unroll
        for (int w = 0; w < T2 / 32; w++) bsum += swarp[w];
        g_partials[blockIdx.x] = bsum;
        __threadfence();
        unsigned old = atomicAdd(&g_ticket, 1u);
        s_last = (old == BLOCKS2 - 1);
    }
    __syncthreads();

    if (s_last) {
        double t = 0.0;
        for (int i = tid; i < BLOCKS2; i += T2) t += g_partials[i];
        #pragma unroll
        for (int off = 16; off > 0; off >>= 1)
            t += __shfl_xor_sync(0xFFFFFFFFu, t, off);
        if ((tid & 31) == 0) swarp[tid >> 5] = t;
        __syncthreads();
        if (tid == 0) {
            double tot = 0.0;
            #pragma unroll
            for (int w = 0; w < T2 / 32; w++) tot += swarp[w];
            float m = (float)(tot / (double)((size_t)NROWS * DIM));
            // vq_loss = fl(fl(mean*0.25) + mean)
            out[(size_t)NROWS * (DIM + 1)] = __fadd_rn(__fmul_rn(m, 0.25f), m);
            g_ticket = 0;   // deterministic across graph replays
        }
    }
}

extern "C" void kernel_launch(void* const* d_in, const int* in_sizes, int n_in,
                              void* d_out, int out_size) {
    const float* enc = (const float*)d_in[0];   // [N, 64] fp32
    const float* W   = (const float*)d_in[1];   // [512, 64] fp32
    float* out = (float*)d_out;                 // [N | N*64 | 1] fp32

    cudaFuncSetAttribute(vq_pass1,
                         cudaFuncAttributeMaxDynamicSharedMemorySize, SMEM1_BYTES);

    dim3 g1(RBLK, 2);
    vq_pass1<<<g1, T1, SMEM1_BYTES>>>(enc, W);
    vq_pass2<<<BLOCKS2, T2>>>(enc, W, out);
}